// round 9
// baseline (speedup 1.0000x reference)
#include <cuda_runtime.h>

#define NN 100000
#define EE 1600000
#define FIN 128
#define HH 64
#define OUTF 32
#define NB_SCAN 98   // ceil(100000/1024)

// ---------------- scratch (device globals; no allocation) ----------------
__device__ int   g_deg[2 * NN];          // zero at load; scan1_k re-zeroes
__device__ float g_h[NN * HH];
__device__ float g_o[NN * HH];
__device__ float g_asrc[NN];
__device__ float g_adst[NN];
__device__ float g_va2[HH];
__device__ float g_vd2[HH];
__device__ int   g_rank[2 * EE];
__device__ int   g_rowptr_loc[2 * NN];
__device__ int   g_bsum[2 * 128];
__device__ int2  g_csr[2 * EE];          // L0: (src, weight_bits); L1: (src,dst)->(src,weight_bits)

// ---------------- plain GEMM [nrows x K] @ [K x 64] ----------------
template <int K, bool RELU>
__global__ void gemm_tile(const float* __restrict__ X, const float* __restrict__ W,
                          float* __restrict__ Y) {
    __shared__ float xs[64][68];
    __shared__ float ws[64][64];
    int tid = threadIdx.x;
    int tn = (tid & 15) * 4;
    int tc = (tid >> 4) * 4;
    int row0 = blockIdx.x * 64;

    float acc[4][4];
#pragma unroll
    for (int i = 0; i < 4; i++)
#pragma unroll
        for (int j = 0; j < 4; j++) acc[i][j] = 0.f;

    for (int k0 = 0; k0 < K; k0 += 64) {
        for (int idx = tid; idx < 64 * 64; idx += 256) {
            int r = idx >> 6, k = idx & 63;
            int row = row0 + r;
            float v = (row < NN) ? X[row * K + k0 + k] : 0.f;
            if (RELU) v = fmaxf(v, 0.f);
            xs[k][r] = v;
        }
        for (int idx = tid; idx < 64 * 64; idx += 256) {
            int k = idx >> 6, c = idx & 63;
            ws[k][c] = W[(k0 + k) * 64 + c];
        }
        __syncthreads();
#pragma unroll 8
        for (int kk = 0; kk < 64; ++kk) {
            float4 a = *(const float4*)&xs[kk][tn];
            float4 b = *(const float4*)&ws[kk][tc];
            acc[0][0] += a.x * b.x; acc[0][1] += a.x * b.y; acc[0][2] += a.x * b.z; acc[0][3] += a.x * b.w;
            acc[1][0] += a.y * b.x; acc[1][1] += a.y * b.y; acc[1][2] += a.y * b.z; acc[1][3] += a.y * b.w;
            acc[2][0] += a.z * b.x; acc[2][1] += a.z * b.y; acc[2][2] += a.z * b.z; acc[2][3] += a.z * b.w;
            acc[3][0] += a.w * b.x; acc[3][1] += a.w * b.y; acc[3][2] += a.w * b.z; acc[3][3] += a.w * b.w;
        }
        __syncthreads();
    }
#pragma unroll
    for (int i = 0; i < 4; i++) {
        int row = row0 + tn + i;
        if (row < NN) {
            float4 v = make_float4(acc[i][0], acc[i][1], acc[i][2], acc[i][3]);
            *(float4*)&Y[row * 64 + tc] = v;
        }
    }
}

// ---------------- attvec: asrc/adst for layer 1 directly from x ------------
// asrc[i] = x_i . (W1 @ att_src1), adst[i] = x_i . (W1 @ att_dst1)
// Block 0 additionally precomputes g_va2/g_vd2 = W2 @ att_{src,dst}2.
__global__ void attvec_k(const float* __restrict__ x,
                         const float* __restrict__ W1,
                         const float* __restrict__ as1, const float* __restrict__ ad1,
                         const float* __restrict__ W2,
                         const float* __restrict__ as2, const float* __restrict__ ad2) {
    __shared__ float va[FIN];
    __shared__ float vd[FIN];
    int tid = threadIdx.x;
    // va1/vd1 per block
    if (tid < 128) {
        float s = 0.f;
        const float* wr = W1 + tid * HH;
#pragma unroll 16
        for (int j = 0; j < HH; j++) s += wr[j] * as1[j];
        va[tid] = s;
    } else {
        int k = tid - 128;
        float s = 0.f;
        const float* wr = W1 + k * HH;
#pragma unroll 16
        for (int j = 0; j < HH; j++) s += wr[j] * ad1[j];
        vd[k] = s;
    }
    // layer-2 vectors (block 0 only)
    if (blockIdx.x == 0 && tid < 128) {
        int k = tid & 63;
        const float* wr = W2 + k * HH;
        const float* av = (tid < 64) ? as2 : ad2;
        float s = 0.f;
#pragma unroll 16
        for (int j = 0; j < HH; j++) s += wr[j] * av[j];
        if (tid < 64) g_va2[k] = s; else g_vd2[k] = s;
    }
    __syncthreads();

    int wid = tid >> 5, lane = tid & 31;
    float4 vaq = *(const float4*)&va[lane * 4];
    float4 vdq = *(const float4*)&vd[lane * 4];
    for (int row = blockIdx.x * 8 + wid; row < NN; row += gridDim.x * 8) {
        float4 xv = *(const float4*)(x + row * FIN + lane * 4);
        float ps = xv.x * vaq.x + xv.y * vaq.y + xv.z * vaq.z + xv.w * vaq.w;
        float pd = xv.x * vdq.x + xv.y * vdq.y + xv.z * vdq.z + xv.w * vdq.w;
#pragma unroll
        for (int off = 16; off; off >>= 1) {
            ps += __shfl_xor_sync(0xffffffffu, ps, off);
            pd += __shfl_xor_sync(0xffffffffu, pd, off);
        }
        if (lane == 0) { g_asrc[row] = ps; g_adst[row] = pd; }
    }
}

// ---------------- CSR build ----------------
__global__ void hist_k(const int* __restrict__ e, int L) {
    int i = blockIdx.x * blockDim.x + threadIdx.x;
    if (i < EE / 2) {
        int2 d2 = ((const int2*)(e + EE))[i];
        int2 r2;
        r2.x = atomicAdd(&g_deg[L * NN + d2.x], 1);
        r2.y = atomicAdd(&g_deg[L * NN + d2.y], 1);
        ((int2*)(g_rank + L * EE))[i] = r2;
    }
}
__global__ void scan1_k(int L) {
    __shared__ int s[1024];
    int tid = threadIdx.x;
    int i = blockIdx.x * 1024 + tid;
    int v = (i < NN) ? g_deg[L * NN + i] : 0;
    if (i < NN) g_deg[L * NN + i] = 0;
    s[tid] = v;
    __syncthreads();
#pragma unroll
    for (int off = 1; off < 1024; off <<= 1) {
        int t = (tid >= off) ? s[tid - off] : 0;
        __syncthreads();
        s[tid] += t;
        __syncthreads();
    }
    if (i < NN) g_rowptr_loc[L * NN + i] = s[tid] - v;
    if (tid == 1023) g_bsum[L * 128 + blockIdx.x] = s[1023];
}
__device__ __forceinline__ void block_prefix(int* sp, int L, int tid) {
    if (tid < 128) {
        int src = tid - 1;
        sp[tid] = (src >= 0 && src < NB_SCAN) ? g_bsum[L * 128 + src] : 0;
    }
    __syncthreads();
#pragma unroll
    for (int off = 1; off < 128; off <<= 1) {
        int t = 0;
        if (tid < 128 && tid >= off) t = sp[tid - off];
        __syncthreads();
        if (tid < 128) sp[tid] += t;
        __syncthreads();
    }
}
// layer-1: scatter positions + fused softmax weights (asrc/adst from attvec)
__global__ void scatterw_k(const int* __restrict__ e) {
    __shared__ int sp[128];
    int tid = threadIdx.x;
    block_prefix(sp, 0, tid);
    int i = blockIdx.x * blockDim.x + tid;
    if (i < EE / 2) {
        int2 d2 = ((const int2*)(e + EE))[i];
        int2 s2 = ((const int2*)e)[i];
        int2 r2 = ((const int2*)g_rank)[i];
        const int* rl = g_rowptr_loc;
        int pos0 = __ldg(&rl[d2.x]) + sp[d2.x >> 10] + r2.x;
        int pos1 = __ldg(&rl[d2.y]) + sp[d2.y >> 10] + r2.y;
        float e0 = __ldg(&g_asrc[s2.x]) + __ldg(&g_adst[d2.x]);
        float e1 = __ldg(&g_asrc[s2.y]) + __ldg(&g_adst[d2.y]);
        e0 = (e0 >= 0.f) ? e0 : 0.2f * e0;
        e1 = (e1 >= 0.f) ? e1 : 0.2f * e1;
        g_csr[pos0] = make_int2(s2.x, __float_as_int(__expf(e0)));
        g_csr[pos1] = make_int2(s2.y, __float_as_int(__expf(e1)));
    }
}
// layer-2: scatter (src,dst) pairs; weights filled later by eweight_k
__global__ void scatter2_k(const int* __restrict__ e) {
    __shared__ int sp[128];
    int tid = threadIdx.x;
    block_prefix(sp, 1, tid);
    int i = blockIdx.x * blockDim.x + tid;
    if (i < EE / 2) {
        int2 d2 = ((const int2*)(e + EE))[i];
        int2 s2 = ((const int2*)e)[i];
        int2 r2 = ((const int2*)(g_rank + EE))[i];
        const int* rl = g_rowptr_loc + NN;
        int pos0 = __ldg(&rl[d2.x]) + sp[d2.x >> 10] + r2.x;
        int pos1 = __ldg(&rl[d2.y]) + sp[d2.y >> 10] + r2.y;
        g_csr[EE + pos0] = make_int2(s2.x, d2.x);
        g_csr[EE + pos1] = make_int2(s2.y, d2.y);
    }
}
// fill layer-2 weights in CSR order (after agg1 wrote asrc2/adst2)
__global__ void eweight_k() {
    int i = blockIdx.x * blockDim.x + threadIdx.x;
    if (i < EE / 2) {
        int4 p = ((const int4*)(g_csr + EE))[i];   // two entries
        float e0 = __ldg(&g_asrc[p.x]) + __ldg(&g_adst[p.y]);
        float e1 = __ldg(&g_asrc[p.z]) + __ldg(&g_adst[p.w]);
        e0 = (e0 >= 0.f) ? e0 : 0.2f * e0;
        e1 = (e1 >= 0.f) ? e1 : 0.2f * e1;
        p.y = __float_as_int(__expf(e0));
        p.w = __float_as_int(__expf(e1));
        ((int4*)(g_csr + EE))[i] = p;
    }
}

// ---------------- aggregate: warp per node, weights precomputed ----------
// EPI: also emit layer-2 attention dots asrc2/adst2 = relu(o)·va2 / ·vd2.
template <bool FINAL, bool EPI>
__global__ void agg_k(const float* __restrict__ h, const float* __restrict__ bias,
                      float* __restrict__ out, int L,
                      const float* __restrict__ Wl, const float* __restrict__ bl) {
    __shared__ int sp[128];
    __shared__ float wsh[64 * 32];
    __shared__ int2 s_e[8][32];
    int tid = threadIdx.x;
    block_prefix(sp, L, tid);
    if (FINAL) {
        for (int i = tid; i < 64 * 32; i += 256) wsh[i] = Wl[i];
        __syncthreads();
    }

    int wid = tid >> 5, lane = tid & 31;
    int node = blockIdx.x * 8 + wid;
    const int* rl = g_rowptr_loc + L * NN;
    int start = __ldg(&rl[node]) + sp[node >> 10];
    int end = (node + 1 == NN) ? EE
              : __ldg(&rl[node + 1]) + sp[(node + 1) >> 10];
    const int2* csr = g_csr + L * EE;

    int half = lane >> 4;
    int q = (lane & 15) * 4;

    float4 acc = make_float4(0.f, 0.f, 0.f, 0.f);
    float ssum = 0.f;

    for (int j0 = start; j0 < end; j0 += 32) {
        int j = j0 + lane;
        int2 p = make_int2(0, 0);
        if (j < end) {
            p = __ldg(&csr[j]);
            ssum += __int_as_float(p.y);
        }
        s_e[wid][lane] = p;
        __syncwarp();
        int cnt = min(32, end - j0);
        int jj = 0;
        for (; jj + 8 <= cnt; jj += 8) {
            int2 p0 = s_e[wid][jj + half];
            int2 p1 = s_e[wid][jj + 2 + half];
            int2 p2 = s_e[wid][jj + 4 + half];
            int2 p3 = s_e[wid][jj + 6 + half];
            float w0 = __int_as_float(p0.y), w1 = __int_as_float(p1.y);
            float w2 = __int_as_float(p2.y), w3 = __int_as_float(p3.y);
            float4 h0 = *(const float4*)(h + p0.x * 64 + q);
            float4 h1 = *(const float4*)(h + p1.x * 64 + q);
            float4 h2 = *(const float4*)(h + p2.x * 64 + q);
            float4 h3 = *(const float4*)(h + p3.x * 64 + q);
            acc.x += w0 * h0.x + w1 * h1.x + w2 * h2.x + w3 * h3.x;
            acc.y += w0 * h0.y + w1 * h1.y + w2 * h2.y + w3 * h3.y;
            acc.z += w0 * h0.z + w1 * h1.z + w2 * h2.z + w3 * h3.z;
            acc.w += w0 * h0.w + w1 * h1.w + w2 * h2.w + w3 * h3.w;
        }
        for (; jj < cnt; jj += 2) {
            int ei = jj + half;
            if (ei < cnt) {
                int2 pv = s_e[wid][ei];
                float wc = __int_as_float(pv.y);
                float4 hv = *(const float4*)(h + pv.x * 64 + q);
                acc.x += wc * hv.x; acc.y += wc * hv.y;
                acc.z += wc * hv.z; acc.w += wc * hv.w;
            }
        }
        __syncwarp();
    }

    acc.x += __shfl_xor_sync(0xffffffffu, acc.x, 16);
    acc.y += __shfl_xor_sync(0xffffffffu, acc.y, 16);
    acc.z += __shfl_xor_sync(0xffffffffu, acc.z, 16);
    acc.w += __shfl_xor_sync(0xffffffffu, acc.w, 16);
#pragma unroll
    for (int off = 16; off; off >>= 1) ssum += __shfl_xor_sync(0xffffffffu, ssum, off);
    float inv = 1.0f / (ssum + 1e-16f);

    float4 b4 = *(const float4*)(bias + q);
    float4 o;
    o.x = acc.x * inv + b4.x; o.y = acc.y * inv + b4.y;
    o.z = acc.z * inv + b4.z; o.w = acc.w * inv + b4.w;

    if (!FINAL) {
        if (half == 0) *(float4*)(out + node * 64 + q) = o;
    }
    if (EPI) {
        // layer-2 attention dots: relu(o) . va2 / vd2 (both halves duplicate -> x2)
        float rx = fmaxf(o.x, 0.f), ry = fmaxf(o.y, 0.f);
        float rz = fmaxf(o.z, 0.f), rw = fmaxf(o.w, 0.f);
        float4 va = *(const float4*)&g_va2[q];
        float4 vd = *(const float4*)&g_vd2[q];
        float ps = rx * va.x + ry * va.y + rz * va.z + rw * va.w;
        float pd = rx * vd.x + ry * vd.y + rz * vd.z + rw * vd.w;
#pragma unroll
        for (int off = 16; off; off >>= 1) {
            ps += __shfl_xor_sync(0xffffffffu, ps, off);
            pd += __shfl_xor_sync(0xffffffffu, pd, off);
        }
        if (lane == 0) { g_asrc[node] = 0.5f * ps; g_adst[node] = 0.5f * pd; }
    }
    if (FINAL) {
        float oarr[4] = {o.x, o.y, o.z, o.w};
        float accl = __ldg(&bl[lane]);
#pragma unroll
        for (int k = 0; k < 64; k++) {
            float xk = __shfl_sync(0xffffffffu, oarr[k & 3], k >> 2);
            accl += xk * wsh[k * 32 + lane];
        }
        float mx = accl;
#pragma unroll
        for (int off = 16; off; off >>= 1) mx = fmaxf(mx, __shfl_xor_sync(0xffffffffu, mx, off));
        float ex = __expf(accl - mx);
        float sum = ex;
#pragma unroll
        for (int off = 16; off; off >>= 1) sum += __shfl_xor_sync(0xffffffffu, sum, off);
        out[node * 32 + lane] = accl - mx - __logf(sum);
    }
}

// ---------------- launch ----------------
extern "C" void kernel_launch(void* const* d_in, const int* in_sizes, int n_in,
                              void* d_out, int out_size) {
    const float* x    = (const float*)d_in[0];
    const int*   ei1  = (const int*)d_in[1];
    const int*   ei2  = (const int*)d_in[2];
    const float* W1   = (const float*)d_in[3];
    const float* as1  = (const float*)d_in[4];
    const float* ad1  = (const float*)d_in[5];
    const float* b1   = (const float*)d_in[6];
    const float* W2   = (const float*)d_in[7];
    const float* as2  = (const float*)d_in[8];
    const float* ad2  = (const float*)d_in[9];
    const float* b2   = (const float*)d_in[10];
    const float* Wlin = (const float*)d_in[11];
    const float* blin = (const float*)d_in[12];
    float* out = (float*)d_out;

    float *h, *o;
    cudaGetSymbolAddress((void**)&h, g_h);
    cudaGetSymbolAddress((void**)&o, g_o);

    static cudaStream_t sA = nullptr, sB = nullptr, sC = nullptr;
    static cudaEvent_t ev_fork, ev_v, ev_csr1, ev_agg1, ev_w2;
    if (sA == nullptr) {
        cudaStreamCreateWithFlags(&sA, cudaStreamNonBlocking);
        cudaStreamCreateWithFlags(&sB, cudaStreamNonBlocking);
        cudaStreamCreateWithFlags(&sC, cudaStreamNonBlocking);
        cudaEventCreateWithFlags(&ev_fork, cudaEventDisableTiming);
        cudaEventCreateWithFlags(&ev_v, cudaEventDisableTiming);
        cudaEventCreateWithFlags(&ev_csr1, cudaEventDisableTiming);
        cudaEventCreateWithFlags(&ev_agg1, cudaEventDisableTiming);
        cudaEventCreateWithFlags(&ev_w2, cudaEventDisableTiming);
    }

    const int gemm_grid = (NN + 63) / 64;
    const int agg_grid  = NN / 8;
    const int egrid2    = (EE / 2 + 255) / 256;

    cudaEventRecord(ev_fork, 0);
    cudaStreamWaitEvent(sA, ev_fork, 0);
    cudaStreamWaitEvent(sB, ev_fork, 0);
    cudaStreamWaitEvent(sC, ev_fork, 0);

    // chain1 (weighted CSR for layer 1) on sA / sC
    hist_k<<<egrid2, 256, 0, sA>>>(ei1, 0);                                  // #1
    scan1_k<<<NB_SCAN, 1024, 0, sA>>>(0);                                    // #2
    attvec_k<<<512, 256, 0, sC>>>(x, W1, as1, ad1, W2, as2, ad2);            // #3
    cudaEventRecord(ev_v, sC);
    cudaStreamWaitEvent(sA, ev_v, 0);
    scatterw_k<<<egrid2, 256, 0, sA>>>(ei1);                                 // #4 <- ncu
    cudaEventRecord(ev_csr1, sA);

    // chain2 (position-only CSR for layer 2) on sB
    hist_k<<<egrid2, 256, 0, sB>>>(ei2, 1);                                  // #5
    scan1_k<<<NB_SCAN, 1024, 0, sB>>>(1);                                    // #6
    scatter2_k<<<egrid2, 256, 0, sB>>>(ei2);                                 // #7

    // main: gemm1 runs from t0, parallel with both chains
    gemm_tile<FIN, false><<<gemm_grid, 256>>>(x, W1, h);                     // #8
    cudaStreamWaitEvent(0, ev_csr1, 0);
    agg_k<false, true><<<agg_grid, 256>>>(h, b1, o, 0, nullptr, nullptr);    // #9
    cudaEventRecord(ev_agg1, 0);

    // layer-2 weight fill on sB (after scatter2 + agg1), parallel with gemm2
    cudaStreamWaitEvent(sB, ev_agg1, 0);
    eweight_k<<<egrid2, 256, 0, sB>>>();                                     // #10
    cudaEventRecord(ev_w2, sB);

    gemm_tile<HH, true><<<gemm_grid, 256>>>(o, W2, h);                       // #11
    cudaStreamWaitEvent(0, ev_w2, 0);
    agg_k<true, false><<<agg_grid, 256>>>(h, b2, out, 1, Wlin, blin);        // #12
}

// round 10
// speedup vs baseline: 1.2466x; 1.2466x over previous
#include <cuda_runtime.h>

#define NN 100000
#define EE 1600000
#define FIN 128
#define HH 64
#define OUTF 32
#define NB_SCAN 98   // ceil(100000/1024)

typedef unsigned long long u64;

// ---------------- scratch (device globals; no allocation) ----------------
__device__ float g_h[NN * HH];
__device__ float g_o[NN * HH];
__device__ float g_asrc[NN];
__device__ float g_adst[NN];
__device__ int   g_deg[2 * NN];
__device__ int   g_rowptr[2 * (NN + 1)];
__device__ int   g_cursor[2 * NN];
__device__ int   g_csr_src[2 * EE];
__device__ int   g_bsum[2 * 128];

// ---------------- f32x2 packed-FMA helpers (sm_103a dual-fp32 path) --------
__device__ __forceinline__ u64 bcast2(float x) {
    u64 r; asm("mov.b64 %0, {%1, %1};" : "=l"(r) : "f"(x)); return r;
}
__device__ __forceinline__ void fma2(u64& d, u64 a, u64 b) {
    asm("fma.rn.f32x2 %0, %1, %2, %0;" : "+l"(d) : "l"(a), "l"(b));
}
__device__ __forceinline__ float2 unpack2(u64 v) {
    float2 r; asm("mov.b64 {%0, %1}, %2;" : "=f"(r.x), "=f"(r.y) : "l"(v)); return r;
}

// ---------------- GEMM + fused attention dots (f32x2 core) ----------------
template <int K, bool RELU>
__global__ void gemm_att(const float* __restrict__ X, const float* __restrict__ W,
                         float* __restrict__ Y,
                         const float* __restrict__ av_s, const float* __restrict__ av_d,
                         int nrows) {
    __shared__ float xs[64][68];
    __shared__ float ws[64][64];
    __shared__ float redp[16][64];
    __shared__ float redd[16][64];
    int tid = threadIdx.x;
    int tn = (tid & 15) * 4;
    int g  = tid >> 4;
    int tc = g * 4;
    int row0 = blockIdx.x * 64;

    // accp[i][0] = cols (tc,tc+1) of row tn+i; accp[i][1] = cols (tc+2,tc+3)
    u64 accp[4][2];
#pragma unroll
    for (int i = 0; i < 4; i++) { accp[i][0] = 0ull; accp[i][1] = 0ull; }

    for (int k0 = 0; k0 < K; k0 += 64) {
        for (int idx = tid; idx < 64 * 64; idx += 256) {
            int r = idx >> 6, k = idx & 63;
            int row = row0 + r;
            float v = (row < nrows) ? X[row * K + k0 + k] : 0.f;
            if (RELU) v = fmaxf(v, 0.f);
            xs[k][r] = v;
        }
        for (int idx = tid; idx < 64 * 64; idx += 256) {
            int k = idx >> 6, c = idx & 63;
            ws[k][c] = W[(k0 + k) * 64 + c];
        }
        __syncthreads();
#pragma unroll 8
        for (int kk = 0; kk < 64; ++kk) {
            float4 a = *(const float4*)&xs[kk][tn];
            ulonglong2 bq = *(const ulonglong2*)&ws[kk][tc];   // (b0,b1),(b2,b3)
            u64 a0 = bcast2(a.x), a1 = bcast2(a.y), a2 = bcast2(a.z), a3 = bcast2(a.w);
            fma2(accp[0][0], a0, bq.x); fma2(accp[0][1], a0, bq.y);
            fma2(accp[1][0], a1, bq.x); fma2(accp[1][1], a1, bq.y);
            fma2(accp[2][0], a2, bq.x); fma2(accp[2][1], a2, bq.y);
            fma2(accp[3][0], a3, bq.x); fma2(accp[3][1], a3, bq.y);
        }
        __syncthreads();
    }

    // unpack accumulators
    float acc[4][4];
#pragma unroll
    for (int i = 0; i < 4; i++) {
        float2 lo = unpack2(accp[i][0]);
        float2 hi = unpack2(accp[i][1]);
        acc[i][0] = lo.x; acc[i][1] = lo.y; acc[i][2] = hi.x; acc[i][3] = hi.y;
    }

    float as0 = av_s[tc], as1 = av_s[tc + 1], as2 = av_s[tc + 2], as3 = av_s[tc + 3];
    float ad0 = av_d[tc], ad1 = av_d[tc + 1], ad2 = av_d[tc + 2], ad3 = av_d[tc + 3];
#pragma unroll
    for (int i = 0; i < 4; i++) {
        int row = row0 + tn + i;
        if (row < nrows) {
            float4 v = make_float4(acc[i][0], acc[i][1], acc[i][2], acc[i][3]);
            *(float4*)&Y[row * 64 + tc] = v;
        }
        redp[g][tn + i] = acc[i][0] * as0 + acc[i][1] * as1 + acc[i][2] * as2 + acc[i][3] * as3;
        redd[g][tn + i] = acc[i][0] * ad0 + acc[i][1] * ad1 + acc[i][2] * ad2 + acc[i][3] * ad3;
    }
    __syncthreads();
    if (tid < 64) {
        int row = row0 + tid;
        float ps = 0.f, pd = 0.f;
#pragma unroll
        for (int c = 0; c < 16; c++) { ps += redp[c][tid]; pd += redd[c][tid]; }
        if (row < nrows) { g_asrc[row] = ps; g_adst[row] = pd; }
    }
}

// ---------------- CSR build (per-graph chains) ----------------
__global__ void zero_k(int L) {
    int i = blockIdx.x * blockDim.x + threadIdx.x;
    if (i < NN) g_deg[L * NN + i] = 0;
}
__global__ void hist_k(const int* __restrict__ e, int L) {
    int i = blockIdx.x * blockDim.x + threadIdx.x;
    if (i < EE) atomicAdd(&g_deg[L * NN + e[EE + i]], 1);
}
__global__ void scan1_k(int L) {
    __shared__ int s[1024];
    int tid = threadIdx.x;
    int i = blockIdx.x * 1024 + tid;
    int v = (i < NN) ? g_deg[L * NN + i] : 0;
    s[tid] = v;
    __syncthreads();
#pragma unroll
    for (int off = 1; off < 1024; off <<= 1) {
        int t = (tid >= off) ? s[tid - off] : 0;
        __syncthreads();
        s[tid] += t;
        __syncthreads();
    }
    if (i < NN) g_rowptr[L * (NN + 1) + i] = s[tid] - v;
    if (tid == 1023) g_bsum[L * 128 + blockIdx.x] = s[1023];
}
__global__ void scan23_k(int L) {
    __shared__ int bpart[128];
    __shared__ int base_s;
    int b = blockIdx.x;
    int tid = threadIdx.x;
    if (tid < 128) bpart[tid] = (tid < b) ? g_bsum[L * 128 + tid] : 0;
    __syncthreads();
    if (tid < 64) bpart[tid] += bpart[tid + 64];
    __syncthreads();
    if (tid < 32) {
        int v = bpart[tid] + bpart[tid + 32];
#pragma unroll
        for (int off = 16; off; off >>= 1) v += __shfl_xor_sync(0xffffffffu, v, off);
        if (tid == 0) base_s = v;
    }
    __syncthreads();
    int i = b * 1024 + tid;
    if (i < NN) {
        int r = g_rowptr[L * (NN + 1) + i] + base_s;
        g_rowptr[L * (NN + 1) + i] = r;
        g_cursor[L * NN + i] = r;
    }
    if (b == 0 && tid == 0) g_rowptr[L * (NN + 1) + NN] = EE;
}
__global__ void scatter_k(const int* __restrict__ e, int L) {
    int i = blockIdx.x * blockDim.x + threadIdx.x;
    if (i < EE) {
        int d = e[EE + i];
        int p = atomicAdd(&g_cursor[L * NN + d], 1);
        g_csr_src[L * EE + p] = e[i];
    }
}

// ---------------- fused segment softmax + aggregate ----------------
// warp per dst node; half-warp per edge, float4 gather, up to 8 edges in flight.
template <bool FINAL>
__global__ void agg_k(const float* __restrict__ h, const float* __restrict__ bias,
                      float* __restrict__ out,
                      const int* __restrict__ rowptr, const int* __restrict__ csr,
                      const float* __restrict__ Wl, const float* __restrict__ bl) {
    __shared__ float wsh[64 * 32];
    if (FINAL) {
        for (int i = threadIdx.x; i < 64 * 32; i += 256) wsh[i] = Wl[i];
        __syncthreads();
    }
    int gw = (blockIdx.x * blockDim.x + threadIdx.x) >> 5;
    int lane = threadIdx.x & 31;
    if (gw >= NN) return;
    int half = lane >> 4;
    int q = (lane & 15) * 4;
    int start = rowptr[gw];
    int end = rowptr[gw + 1];
    float ad = g_adst[gw];

    float4 acc = make_float4(0.f, 0.f, 0.f, 0.f);
    float ssum = 0.f;
    for (int j0 = start; j0 < end; j0 += 32) {
        int j = j0 + lane;
        int s = 0; float w = 0.f;
        if (j < end) {
            s = csr[j];
            float e = __ldg(&g_asrc[s]) + ad;
            e = (e >= 0.f) ? e : 0.2f * e;
            w = __expf(e);
        }
        ssum += w;
        int cnt = min(32, end - j0);
        int p2 = 0;
        for (; p2 + 8 <= cnt; p2 += 8) {
            int e0 = p2 + half, e1 = p2 + 2 + half, e2 = p2 + 4 + half, e3 = p2 + 6 + half;
            float w0 = __shfl_sync(0xffffffffu, w, e0);
            int   s0 = __shfl_sync(0xffffffffu, s, e0);
            float w1 = __shfl_sync(0xffffffffu, w, e1);
            int   s1 = __shfl_sync(0xffffffffu, s, e1);
            float w2 = __shfl_sync(0xffffffffu, w, e2);
            int   s2 = __shfl_sync(0xffffffffu, s, e2);
            float w3 = __shfl_sync(0xffffffffu, w, e3);
            int   s3 = __shfl_sync(0xffffffffu, s, e3);
            float4 h0 = *(const float4*)(h + s0 * 64 + q);
            float4 h1 = *(const float4*)(h + s1 * 64 + q);
            float4 h2 = *(const float4*)(h + s2 * 64 + q);
            float4 h3 = *(const float4*)(h + s3 * 64 + q);
            acc.x += w0 * h0.x + w1 * h1.x + w2 * h2.x + w3 * h3.x;
            acc.y += w0 * h0.y + w1 * h1.y + w2 * h2.y + w3 * h3.y;
            acc.z += w0 * h0.z + w1 * h1.z + w2 * h2.z + w3 * h3.z;
            acc.w += w0 * h0.w + w1 * h1.w + w2 * h2.w + w3 * h3.w;
        }
        for (; p2 < cnt; p2 += 2) {
            int ei = p2 + half;
            int eic = (ei < cnt) ? ei : (cnt - 1);
            float wc = __shfl_sync(0xffffffffu, w, eic);
            int   sc = __shfl_sync(0xffffffffu, s, eic);
            if (ei < cnt) {
                float4 hv = *(const float4*)(h + sc * 64 + q);
                acc.x += wc * hv.x; acc.y += wc * hv.y;
                acc.z += wc * hv.z; acc.w += wc * hv.w;
            }
        }
    }
    acc.x += __shfl_xor_sync(0xffffffffu, acc.x, 16);
    acc.y += __shfl_xor_sync(0xffffffffu, acc.y, 16);
    acc.z += __shfl_xor_sync(0xffffffffu, acc.z, 16);
    acc.w += __shfl_xor_sync(0xffffffffu, acc.w, 16);
#pragma unroll
    for (int off = 16; off; off >>= 1) ssum += __shfl_xor_sync(0xffffffffu, ssum, off);
    float inv = 1.0f / (ssum + 1e-16f);

    float4 b4 = *(const float4*)(bias + q);
    float4 o;
    o.x = acc.x * inv + b4.x; o.y = acc.y * inv + b4.y;
    o.z = acc.z * inv + b4.z; o.w = acc.w * inv + b4.w;

    if (!FINAL) {
        if (half == 0) *(float4*)(out + gw * 64 + q) = o;
    } else {
        float oarr[4] = {o.x, o.y, o.z, o.w};
        float accl = __ldg(&bl[lane]);
#pragma unroll
        for (int k = 0; k < 64; k++) {
            float xk = __shfl_sync(0xffffffffu, oarr[k & 3], k >> 2);
            accl += xk * wsh[k * 32 + lane];
        }
        float mx = accl;
#pragma unroll
        for (int off = 16; off; off >>= 1) mx = fmaxf(mx, __shfl_xor_sync(0xffffffffu, mx, off));
        float ex = __expf(accl - mx);
        float sum = ex;
#pragma unroll
        for (int off = 16; off; off >>= 1) sum += __shfl_xor_sync(0xffffffffu, sum, off);
        out[gw * 32 + lane] = accl - mx - __logf(sum);
    }
}

// ---------------- launch (R4 champion schedule) ----------------
extern "C" void kernel_launch(void* const* d_in, const int* in_sizes, int n_in,
                              void* d_out, int out_size) {
    const float* x    = (const float*)d_in[0];
    const int*   ei1  = (const int*)d_in[1];
    const int*   ei2  = (const int*)d_in[2];
    const float* W1   = (const float*)d_in[3];
    const float* as1  = (const float*)d_in[4];
    const float* ad1  = (const float*)d_in[5];
    const float* b1   = (const float*)d_in[6];
    const float* W2   = (const float*)d_in[7];
    const float* as2  = (const float*)d_in[8];
    const float* ad2  = (const float*)d_in[9];
    const float* b2   = (const float*)d_in[10];
    const float* Wlin = (const float*)d_in[11];
    const float* blin = (const float*)d_in[12];
    float* out = (float*)d_out;

    float *h, *o;
    int *rowptr, *csr;
    cudaGetSymbolAddress((void**)&h, g_h);
    cudaGetSymbolAddress((void**)&o, g_o);
    cudaGetSymbolAddress((void**)&rowptr, g_rowptr);
    cudaGetSymbolAddress((void**)&csr, g_csr_src);

    static cudaStream_t s1 = nullptr, s2 = nullptr;
    static cudaEvent_t ev_fork = nullptr, ev_csr1 = nullptr, ev_csr2 = nullptr;
    if (s1 == nullptr) {
        cudaStreamCreateWithFlags(&s1, cudaStreamNonBlocking);
        cudaStreamCreateWithFlags(&s2, cudaStreamNonBlocking);
        cudaEventCreateWithFlags(&ev_fork, cudaEventDisableTiming);
        cudaEventCreateWithFlags(&ev_csr1, cudaEventDisableTiming);
        cudaEventCreateWithFlags(&ev_csr2, cudaEventDisableTiming);
    }

    const int gemm_grid = (NN + 63) / 64;
    const int warp_grid = (NN + 7) / 8;
    const int egrid = EE / 256;
    const int ngrid = (NN + 255) / 256;

    cudaEventRecord(ev_fork, 0);
    cudaStreamWaitEvent(s1, ev_fork, 0);
    cudaStreamWaitEvent(s2, ev_fork, 0);

    zero_k<<<ngrid, 256, 0, s1>>>(0);
    hist_k<<<egrid, 256, 0, s1>>>(ei1, 0);
    scan1_k<<<NB_SCAN, 1024, 0, s1>>>(0);
    scan23_k<<<NB_SCAN, 1024, 0, s1>>>(0);
    scatter_k<<<egrid, 256, 0, s1>>>(ei1, 0);
    cudaEventRecord(ev_csr1, s1);

    zero_k<<<ngrid, 256, 0, s2>>>(1);
    hist_k<<<egrid, 256, 0, s2>>>(ei2, 1);
    scan1_k<<<NB_SCAN, 1024, 0, s2>>>(1);
    scan23_k<<<NB_SCAN, 1024, 0, s2>>>(1);
    scatter_k<<<egrid, 256, 0, s2>>>(ei2, 1);
    cudaEventRecord(ev_csr2, s2);

    gemm_att<FIN, false><<<gemm_grid, 256>>>(x, W1, h, as1, ad1, NN);
    cudaStreamWaitEvent(0, ev_csr1, 0);
    agg_k<false><<<warp_grid, 256>>>(h, b1, o, rowptr, csr, nullptr, nullptr);
    gemm_att<HH, true><<<gemm_grid, 256>>>(o, W2, h, as2, ad2, NN);
    cudaStreamWaitEvent(0, ev_csr2, 0);
    agg_k<true><<<warp_grid, 256>>>(h, b2, out, rowptr + (NN + 1), csr + EE,
                                    Wlin, blin);
}

// round 11
// speedup vs baseline: 1.2852x; 1.0310x over previous
#include <cuda_runtime.h>

#define NN 100000
#define EE 1600000
#define FIN 128
#define HH 64
#define OUTF 32
#define NB_SCAN 98   // ceil(100000/1024)

typedef unsigned long long u64;

// ---------------- scratch (device globals; no allocation) ----------------
// g_deg starts zero (static init); scan1_k re-zeroes after consuming.
__device__ int   g_deg[2 * NN];
__device__ float g_h[NN * HH];
__device__ float g_o[NN * HH];
__device__ float g_asrc[NN];
__device__ float g_adst[NN];
__device__ int   g_rowptr[2 * (NN + 1)];
__device__ int   g_cursor[2 * NN];
__device__ int   g_csr_src[2 * EE];
__device__ int   g_bsum[2 * 128];

// ---------------- f32x2 packed-FMA helpers ----------------
__device__ __forceinline__ u64 bcast2(float x) {
    u64 r; asm("mov.b64 %0, {%1, %1};" : "=l"(r) : "f"(x)); return r;
}
__device__ __forceinline__ void fma2(u64& d, u64 a, u64 b) {
    asm("fma.rn.f32x2 %0, %1, %2, %0;" : "+l"(d) : "l"(a), "l"(b));
}
__device__ __forceinline__ float2 unpack2(u64 v) {
    float2 r; asm("mov.b64 {%0, %1}, %2;" : "=f"(r.x), "=f"(r.y) : "l"(v)); return r;
}

// ---------------- GEMM + fused attention dots (f32x2 core) ----------------
template <int K, bool RELU>
__global__ void gemm_att(const float* __restrict__ X, const float* __restrict__ W,
                         float* __restrict__ Y,
                         const float* __restrict__ av_s, const float* __restrict__ av_d,
                         int nrows) {
    __shared__ float xs[64][68];
    __shared__ float ws[64][64];
    __shared__ float redp[16][64];
    __shared__ float redd[16][64];
    int tid = threadIdx.x;
    int tn = (tid & 15) * 4;
    int g  = tid >> 4;
    int tc = g * 4;
    int row0 = blockIdx.x * 64;

    u64 accp[4][2];
#pragma unroll
    for (int i = 0; i < 4; i++) { accp[i][0] = 0ull; accp[i][1] = 0ull; }

    for (int k0 = 0; k0 < K; k0 += 64) {
        for (int idx = tid; idx < 64 * 64; idx += 256) {
            int r = idx >> 6, k = idx & 63;
            int row = row0 + r;
            float v = (row < nrows) ? X[row * K + k0 + k] : 0.f;
            if (RELU) v = fmaxf(v, 0.f);
            xs[k][r] = v;
        }
        for (int idx = tid; idx < 64 * 64; idx += 256) {
            int k = idx >> 6, c = idx & 63;
            ws[k][c] = W[(k0 + k) * 64 + c];
        }
        __syncthreads();
#pragma unroll 8
        for (int kk = 0; kk < 64; ++kk) {
            float4 a = *(const float4*)&xs[kk][tn];
            ulonglong2 bq = *(const ulonglong2*)&ws[kk][tc];
            u64 a0 = bcast2(a.x), a1 = bcast2(a.y), a2 = bcast2(a.z), a3 = bcast2(a.w);
            fma2(accp[0][0], a0, bq.x); fma2(accp[0][1], a0, bq.y);
            fma2(accp[1][0], a1, bq.x); fma2(accp[1][1], a1, bq.y);
            fma2(accp[2][0], a2, bq.x); fma2(accp[2][1], a2, bq.y);
            fma2(accp[3][0], a3, bq.x); fma2(accp[3][1], a3, bq.y);
        }
        __syncthreads();
    }

    float acc[4][4];
#pragma unroll
    for (int i = 0; i < 4; i++) {
        float2 lo = unpack2(accp[i][0]);
        float2 hi = unpack2(accp[i][1]);
        acc[i][0] = lo.x; acc[i][1] = lo.y; acc[i][2] = hi.x; acc[i][3] = hi.y;
    }

    float as0 = av_s[tc], as1 = av_s[tc + 1], as2 = av_s[tc + 2], as3 = av_s[tc + 3];
    float ad0 = av_d[tc], ad1 = av_d[tc + 1], ad2 = av_d[tc + 2], ad3 = av_d[tc + 3];
#pragma unroll
    for (int i = 0; i < 4; i++) {
        int row = row0 + tn + i;
        if (row < nrows) {
            float4 v = make_float4(acc[i][0], acc[i][1], acc[i][2], acc[i][3]);
            *(float4*)&Y[row * 64 + tc] = v;
        }
        redp[g][tn + i] = acc[i][0] * as0 + acc[i][1] * as1 + acc[i][2] * as2 + acc[i][3] * as3;
        redd[g][tn + i] = acc[i][0] * ad0 + acc[i][1] * ad1 + acc[i][2] * ad2 + acc[i][3] * ad3;
    }
    __syncthreads();
    if (tid < 64) {
        int row = row0 + tid;
        float ps = 0.f, pd = 0.f;
#pragma unroll
        for (int c = 0; c < 16; c++) { ps += redp[c][tid]; pd += redd[c][tid]; }
        if (row < nrows) { g_asrc[row] = ps; g_adst[row] = pd; }
    }
}

// ---------------- CSR build (both graphs per kernel) ----------------
__global__ void hist2_k(const int* __restrict__ e1, const int* __restrict__ e2) {
    int i = blockIdx.x * blockDim.x + threadIdx.x;   // [0, 2E)
    int L = (i >= EE);
    const int* e = L ? e2 : e1;
    int idx = L ? (i - EE) : i;
    atomicAdd(&g_deg[L * NN + e[EE + idx]], 1);
}
__global__ void scan1_k() {
    __shared__ int s[1024];
    int L = blockIdx.y;
    int tid = threadIdx.x;
    int i = blockIdx.x * 1024 + tid;
    int v = (i < NN) ? g_deg[L * NN + i] : 0;
    if (i < NN) g_deg[L * NN + i] = 0;      // reset for next call
    s[tid] = v;
    __syncthreads();
#pragma unroll
    for (int off = 1; off < 1024; off <<= 1) {
        int t = (tid >= off) ? s[tid - off] : 0;
        __syncthreads();
        s[tid] += t;
        __syncthreads();
    }
    if (i < NN) g_rowptr[L * (NN + 1) + i] = s[tid] - v;
    if (tid == 1023) g_bsum[L * 128 + blockIdx.x] = s[1023];
}
__global__ void scan23_k() {
    __shared__ int bpart[128];
    __shared__ int base_s;
    int L = blockIdx.y;
    int b = blockIdx.x;
    int tid = threadIdx.x;
    if (tid < 128) bpart[tid] = (tid < b) ? g_bsum[L * 128 + tid] : 0;
    __syncthreads();
    if (tid < 64) bpart[tid] += bpart[tid + 64];
    __syncthreads();
    if (tid < 32) {
        int v = bpart[tid] + bpart[tid + 32];
#pragma unroll
        for (int off = 16; off; off >>= 1) v += __shfl_xor_sync(0xffffffffu, v, off);
        if (tid == 0) base_s = v;
    }
    __syncthreads();
    int i = b * 1024 + tid;
    if (i < NN) {
        int r = g_rowptr[L * (NN + 1) + i] + base_s;
        g_rowptr[L * (NN + 1) + i] = r;
        g_cursor[L * NN + i] = r;
    }
    if (b == 0 && tid == 0) g_rowptr[L * (NN + 1) + NN] = EE;
}
__global__ void scatter2_k(const int* __restrict__ e1, const int* __restrict__ e2) {
    int i = blockIdx.x * blockDim.x + threadIdx.x;   // [0, 2E)
    int L = (i >= EE);
    const int* e = L ? e2 : e1;
    int idx = L ? (i - EE) : i;
    int d = e[EE + idx];
    int p = atomicAdd(&g_cursor[L * NN + d], 1);
    g_csr_src[L * EE + p] = e[idx];
}

// ---------------- fused segment softmax + aggregate ----------------
template <bool FINAL>
__global__ void agg_k(const float* __restrict__ h, const float* __restrict__ bias,
                      float* __restrict__ out,
                      const int* __restrict__ rowptr, const int* __restrict__ csr,
                      const float* __restrict__ Wl, const float* __restrict__ bl) {
    __shared__ float wsh[64 * 32];
    if (FINAL) {
        for (int i = threadIdx.x; i < 64 * 32; i += 256) wsh[i] = Wl[i];
        __syncthreads();
    }
    int gw = (blockIdx.x * blockDim.x + threadIdx.x) >> 5;
    int lane = threadIdx.x & 31;
    if (gw >= NN) return;
    int half = lane >> 4;
    int q = (lane & 15) * 4;
    int start = rowptr[gw];
    int end = rowptr[gw + 1];
    float ad = g_adst[gw];

    float4 acc = make_float4(0.f, 0.f, 0.f, 0.f);
    float ssum = 0.f;
    for (int j0 = start; j0 < end; j0 += 32) {
        int j = j0 + lane;
        int s = 0; float w = 0.f;
        if (j < end) {
            s = csr[j];
            float e = __ldg(&g_asrc[s]) + ad;
            e = (e >= 0.f) ? e : 0.2f * e;
            w = __expf(e);
        }
        ssum += w;
        int cnt = min(32, end - j0);
        int p2 = 0;
        for (; p2 + 8 <= cnt; p2 += 8) {
            int e0 = p2 + half, e1 = p2 + 2 + half, e2 = p2 + 4 + half, e3 = p2 + 6 + half;
            float w0 = __shfl_sync(0xffffffffu, w, e0);
            int   s0 = __shfl_sync(0xffffffffu, s, e0);
            float w1 = __shfl_sync(0xffffffffu, w, e1);
            int   s1 = __shfl_sync(0xffffffffu, s, e1);
            float w2 = __shfl_sync(0xffffffffu, w, e2);
            int   s2 = __shfl_sync(0xffffffffu, s, e2);
            float w3 = __shfl_sync(0xffffffffu, w, e3);
            int   s3 = __shfl_sync(0xffffffffu, s, e3);
            float4 h0 = *(const float4*)(h + s0 * 64 + q);
            float4 h1 = *(const float4*)(h + s1 * 64 + q);
            float4 h2 = *(const float4*)(h + s2 * 64 + q);
            float4 h3 = *(const float4*)(h + s3 * 64 + q);
            acc.x += w0 * h0.x + w1 * h1.x + w2 * h2.x + w3 * h3.x;
            acc.y += w0 * h0.y + w1 * h1.y + w2 * h2.y + w3 * h3.y;
            acc.z += w0 * h0.z + w1 * h1.z + w2 * h2.z + w3 * h3.z;
            acc.w += w0 * h0.w + w1 * h1.w + w2 * h2.w + w3 * h3.w;
        }
        for (; p2 < cnt; p2 += 2) {
            int ei = p2 + half;
            int eic = (ei < cnt) ? ei : (cnt - 1);
            float wc = __shfl_sync(0xffffffffu, w, eic);
            int   sc = __shfl_sync(0xffffffffu, s, eic);
            if (ei < cnt) {
                float4 hv = *(const float4*)(h + sc * 64 + q);
                acc.x += wc * hv.x; acc.y += wc * hv.y;
                acc.z += wc * hv.z; acc.w += wc * hv.w;
            }
        }
    }
    acc.x += __shfl_xor_sync(0xffffffffu, acc.x, 16);
    acc.y += __shfl_xor_sync(0xffffffffu, acc.y, 16);
    acc.z += __shfl_xor_sync(0xffffffffu, acc.z, 16);
    acc.w += __shfl_xor_sync(0xffffffffu, acc.w, 16);
#pragma unroll
    for (int off = 16; off; off >>= 1) ssum += __shfl_xor_sync(0xffffffffu, ssum, off);
    float inv = 1.0f / (ssum + 1e-16f);

    float4 b4 = *(const float4*)(bias + q);
    float4 o;
    o.x = acc.x * inv + b4.x; o.y = acc.y * inv + b4.y;
    o.z = acc.z * inv + b4.z; o.w = acc.w * inv + b4.w;

    if (!FINAL) {
        if (half == 0) *(float4*)(out + gw * 64 + q) = o;
    } else {
        float oarr[4] = {o.x, o.y, o.z, o.w};
        float accl = __ldg(&bl[lane]);
#pragma unroll
        for (int k = 0; k < 64; k++) {
            float xk = __shfl_sync(0xffffffffu, oarr[k & 3], k >> 2);
            accl += xk * wsh[k * 32 + lane];
        }
        float mx = accl;
#pragma unroll
        for (int off = 16; off; off >>= 1) mx = fmaxf(mx, __shfl_xor_sync(0xffffffffu, mx, off));
        float ex = __expf(accl - mx);
        float sum = ex;
#pragma unroll
        for (int off = 16; off; off >>= 1) sum += __shfl_xor_sync(0xffffffffu, sum, off);
        out[gw * 32 + lane] = accl - mx - __logf(sum);
    }
}

// ---------------- launch: 8 kernels; gemm1 is submission #4 (ncu slot) -------
extern "C" void kernel_launch(void* const* d_in, const int* in_sizes, int n_in,
                              void* d_out, int out_size) {
    const float* x    = (const float*)d_in[0];
    const int*   ei1  = (const int*)d_in[1];
    const int*   ei2  = (const int*)d_in[2];
    const float* W1   = (const float*)d_in[3];
    const float* as1  = (const float*)d_in[4];
    const float* ad1  = (const float*)d_in[5];
    const float* b1   = (const float*)d_in[6];
    const float* W2   = (const float*)d_in[7];
    const float* as2  = (const float*)d_in[8];
    const float* ad2  = (const float*)d_in[9];
    const float* b2   = (const float*)d_in[10];
    const float* Wlin = (const float*)d_in[11];
    const float* blin = (const float*)d_in[12];
    float* out = (float*)d_out;

    float *h, *o;
    int *rowptr, *csr;
    cudaGetSymbolAddress((void**)&h, g_h);
    cudaGetSymbolAddress((void**)&o, g_o);
    cudaGetSymbolAddress((void**)&rowptr, g_rowptr);
    cudaGetSymbolAddress((void**)&csr, g_csr_src);

    static cudaStream_t s1 = nullptr;
    static cudaEvent_t ev_fork = nullptr, ev_csr = nullptr;
    if (s1 == nullptr) {
        cudaStreamCreateWithFlags(&s1, cudaStreamNonBlocking);
        cudaEventCreateWithFlags(&ev_fork, cudaEventDisableTiming);
        cudaEventCreateWithFlags(&ev_csr, cudaEventDisableTiming);
    }

    const int gemm_grid = (NN + 63) / 64;
    const int warp_grid = (NN + 7) / 8;
    const int egrid2 = 2 * EE / 256;     // both graphs, 1 edge/thread

    cudaEventRecord(ev_fork, 0);
    cudaStreamWaitEvent(s1, ev_fork, 0);

    // CSR for BOTH graphs on s1 (submissions #1-#3, #5)
    hist2_k<<<egrid2, 256, 0, s1>>>(ei1, ei2);                                // #1
    scan1_k<<<dim3(NB_SCAN, 2), 1024, 0, s1>>>();                             // #2
    scan23_k<<<dim3(NB_SCAN, 2), 1024, 0, s1>>>();                            // #3
    // gemm1 on main stream — executes from t0, submission slot #4 for ncu
    gemm_att<FIN, false><<<gemm_grid, 256>>>(x, W1, h, as1, ad1, NN);         // #4 <- ncu
    scatter2_k<<<egrid2, 256, 0, s1>>>(ei1, ei2);                             // #5
    cudaEventRecord(ev_csr, s1);

    cudaStreamWaitEvent(0, ev_csr, 0);
    agg_k<false><<<warp_grid, 256>>>(h, b1, o, rowptr, csr, nullptr, nullptr);// #6
    gemm_att<HH, true><<<gemm_grid, 256>>>(o, W2, h, as2, ad2, NN);           // #7
    agg_k<true><<<warp_grid, 256>>>(h, b2, out, rowptr + (NN + 1), csr + EE,
                                    Wlin, blin);                              // #8
}